// round 4
// baseline (speedup 1.0000x reference)
#include <cuda_runtime.h>
#include <cstdint>

#define NNODES 50000
#define NEDGES 800000
#define HID 64

// ---------------- scratch (static device globals; no allocation) ----------------
__device__ float    g_h[NNODES * HID];
__device__ float    g_s[NNODES];
__device__ float    g_d[NNODES];
__device__ unsigned g_menc[NNODES];
__device__ float    g_den[NNODES];
__device__ float    g_agg[NNODES * HID];
__device__ float    g_y0[NNODES * HID];
__device__ float    g_y1[NNODES * HID];
__device__ float    g_y4[NNODES * HID];
__device__ float    g_logit[NEDGES];
__device__ float    g_bufA[(size_t)NEDGES * 128];
__device__ float    g_bufB[(size_t)NEDGES * 128];
__device__ float    g_we[4];

// ---------------- helpers ----------------
__device__ __forceinline__ unsigned ord_enc(float f) {
    unsigned u = __float_as_uint(f);
    return (u & 0x80000000u) ? ~u : (u | 0x80000000u);
}
__device__ __forceinline__ float ord_dec(unsigned u) {
    return (u & 0x80000000u) ? __uint_as_float(u ^ 0x80000000u) : __uint_as_float(~u);
}

// ---------------- tiny prep: w = We @ ae for both GAT layers ----------------
__global__ void k_prep_we(const float* __restrict__ We1, const float* __restrict__ ae1,
                          const float* __restrict__ We2, const float* __restrict__ ae2) {
    int t = threadIdx.x;
    if (t < 4) {
        const float* W = (t < 2) ? We1 : We2;
        const float* a = (t < 2) ? ae1 : ae2;
        int r = t & 1;
        float s = 0.f;
        for (int j = 0; j < HID; j++) s += W[r * HID + j] * a[j];
        g_we[t] = s;
    }
}

// ---------------- per-call re-init of aggregation scratch ----------------
__global__ void k_init() {
    int gid = blockIdx.x * blockDim.x + threadIdx.x;
    if (gid < NNODES * HID) g_agg[gid] = 0.f;
    if (gid < NNODES) { g_den[gid] = 0.f; g_menc[gid] = 0x007fffffu; /* enc(-inf) */ }
}

// ---------------- node GEMM: H = X @ W (MODE0: +scores; MODE1: relu(X1+X2 gemm + bias)) ----
template <int K, int MODE>
__global__ __launch_bounds__(128) void k_node_gemm(
    const float* __restrict__ X, const float* __restrict__ X2,
    const float* __restrict__ W, const float* __restrict__ v1,
    const float* __restrict__ v2,
    float* __restrict__ H, float* __restrict__ S, float* __restrict__ D) {
    __shared__ float Ws[K * HID];
    __shared__ float sv1[HID], sv2[HID];
    int tid = threadIdx.x;
    for (int i = tid; i < K * HID; i += 128) Ws[i] = W[i];
    if (tid < HID) {
        sv1[tid] = v1 ? v1[tid] : 0.f;
        sv2[tid] = v2 ? v2[tid] : 0.f;
    }
    __syncthreads();
    int node = blockIdx.x * 128 + tid;
    if (node >= NNODES) return;

    float acc[HID];
#pragma unroll
    for (int n = 0; n < HID; n++) acc[n] = 0.f;

    const float4* xr = reinterpret_cast<const float4*>(X + (size_t)node * K);
    const float4* xr2 = (MODE == 1) ? reinterpret_cast<const float4*>(X2 + (size_t)node * K) : nullptr;
#pragma unroll 1
    for (int k4 = 0; k4 < K / 4; k4++) {
        float4 v = __ldg(xr + k4);
        if (MODE == 1) {
            float4 w = __ldg(xr2 + k4);
            v.x += w.x; v.y += w.y; v.z += w.z; v.w += w.w;
        }
        float xv[4] = {v.x, v.y, v.z, v.w};
#pragma unroll
        for (int kk = 0; kk < 4; kk++) {
            const float* wr = &Ws[(k4 * 4 + kk) * HID];
#pragma unroll
            for (int n = 0; n < HID; n++) acc[n] = fmaf(xv[kk], wr[n], acc[n]);
        }
    }

    if (MODE == 0) {
        float s = 0.f, d = 0.f;
#pragma unroll
        for (int n = 0; n < HID; n++) { s += acc[n] * sv1[n]; d += acc[n] * sv2[n]; }
        S[node] = s;
        D[node] = d;
    } else {
#pragma unroll
        for (int n = 0; n < HID; n++) acc[n] = fmaxf(acc[n] + sv1[n], 0.f);
    }
    float4* hr = reinterpret_cast<float4*>(H + (size_t)node * HID);
#pragma unroll
    for (int i = 0; i < HID / 4; i++)
        hr[i] = make_float4(acc[4 * i], acc[4 * i + 1], acc[4 * i + 2], acc[4 * i + 3]);
}

// ---------------- edge logit + segment max ----------------
__global__ void k_edge_logit(const int* __restrict__ EI, const float* __restrict__ EA, int which) {
    int e = blockIdx.x * blockDim.x + threadIdx.x;
    if (e >= NEDGES) return;
    int src = __ldg(EI + e);
    int dst = __ldg(EI + NEDGES + e);
    float w0 = g_we[which * 2], w1 = g_we[which * 2 + 1];
    float lg = __ldg(&g_s[src]) + __ldg(&g_d[dst]) + __ldg(EA + 2 * e) * w0 + __ldg(EA + 2 * e + 1) * w1;
    lg = (lg > 0.f) ? lg : 0.2f * lg;  // leaky_relu, slope 0.2
    g_logit[e] = lg;
    atomicMax(&g_menc[dst], ord_enc(lg));
}

// ---------------- edge exp + den + unnormalized aggregation ----------------
__global__ void k_edge_exp_agg(const int* __restrict__ EI) {
    long long gid = (long long)blockIdx.x * blockDim.x + threadIdx.x;
    int e = (int)(gid >> 6);
    int n = (int)(gid & 63);
    if (e >= NEDGES) return;
    int src = __ldg(EI + e);
    int dst = __ldg(EI + NEDGES + e);
    float m = ord_dec(g_menc[dst]);
    float ex = expf(g_logit[e] - m);
    float val = ex * __ldg(&g_h[(size_t)src * HID + n]);
    atomicAdd(&g_agg[(size_t)dst * HID + n], val);
    if (n == 0) atomicAdd(&g_den[dst], ex);
}

// ---------------- normalize + bias + relu ----------------
__global__ void k_node_fin(const float* __restrict__ bias, float* __restrict__ Y) {
    int gid = blockIdx.x * blockDim.x + threadIdx.x;
    if (gid >= NNODES * HID) return;
    int n = gid & 63;
    float den = fmaxf(g_den[gid >> 6], 1e-16f);
    Y[gid] = fmaxf(g_agg[gid] / den + __ldg(bias + n), 0.f);
}

// ---------------- build concat([y4[src]+y4[dst], relu(ea@We0+be0)]) ----------------
__global__ __launch_bounds__(128) void k_build_xb(
    const int* __restrict__ EI, const float* __restrict__ EA,
    const float* __restrict__ We0, const float* __restrict__ be0,
    const float* __restrict__ Y4, float* __restrict__ XB) {
    int e = blockIdx.x;
    int c = threadIdx.x;
    int src = __ldg(EI + e);
    int dst = __ldg(EI + NEDGES + e);
    float v;
    if (c < HID) {
        v = __ldg(&Y4[(size_t)src * HID + c]) + __ldg(&Y4[(size_t)dst * HID + c]);
    } else {
        int c2 = c - HID;
        v = fmaxf(__ldg(EA + 2 * e) * __ldg(We0 + c2) + __ldg(EA + 2 * e + 1) * __ldg(We0 + HID + c2)
                      + __ldg(be0 + c2),
                  0.f);
    }
    XB[(size_t)e * 128 + c] = v;
}

// ---------------- register-tiled SGEMM: C = act(A @ B + bias) ----------------
template <int BM, int BN, int BK, int TM, int TN, bool RELU>
__global__ __launch_bounds__((BM / TM) * (BN / TN)) void k_gemm(
    const float* __restrict__ A, const float* __restrict__ B,
    const float* __restrict__ bias, float* __restrict__ C,
    int M, int N, int K) {
    constexpr int TX = BN / TN;
    constexpr int TY = BM / TM;
    constexpr int NT = TX * TY;
    __shared__ float As[BK][BM];
    __shared__ float Bs[BK][BN];

    int tid = threadIdx.x;
    int tx = tid % TX, ty = tid / TX;
    int m0 = blockIdx.x * BM;
    int n0 = blockIdx.y * BN;

    float acc[TM][TN];
#pragma unroll
    for (int i = 0; i < TM; i++)
#pragma unroll
        for (int j = 0; j < TN; j++) acc[i][j] = 0.f;

    for (int kb = 0; kb < K; kb += BK) {
        // A tile (M multiple of BM, K multiple of BK)
#pragma unroll
        for (int i = tid; i < BM * BK / 4; i += NT) {
            int row = i / (BK / 4);
            int kc = (i % (BK / 4)) * 4;
            float4 v = *reinterpret_cast<const float4*>(A + (size_t)(m0 + row) * K + kb + kc);
            As[kc + 0][row] = v.x;
            As[kc + 1][row] = v.y;
            As[kc + 2][row] = v.z;
            As[kc + 3][row] = v.w;
        }
        // B tile (guard columns for N not multiple of BN)
#pragma unroll
        for (int i = tid; i < BK * BN; i += NT) {
            int row = i / BN;
            int c = i % BN;
            int gc = n0 + c;
            Bs[row][c] = (gc < N) ? __ldg(B + (size_t)(kb + row) * N + gc) : 0.f;
        }
        __syncthreads();
#pragma unroll
        for (int k = 0; k < BK; k++) {
            float a[TM], b[TN];
            if constexpr (TM % 4 == 0) {
                const float4* ap = reinterpret_cast<const float4*>(&As[k][ty * TM]);
#pragma unroll
                for (int i = 0; i < TM / 4; i++) {
                    float4 v = ap[i];
                    a[4 * i] = v.x; a[4 * i + 1] = v.y; a[4 * i + 2] = v.z; a[4 * i + 3] = v.w;
                }
            } else {
#pragma unroll
                for (int i = 0; i < TM; i++) a[i] = As[k][ty * TM + i];
            }
            if constexpr (TN % 4 == 0) {
                const float4* bp = reinterpret_cast<const float4*>(&Bs[k][tx * TN]);
#pragma unroll
                for (int j = 0; j < TN / 4; j++) {
                    float4 v = bp[j];
                    b[4 * j] = v.x; b[4 * j + 1] = v.y; b[4 * j + 2] = v.z; b[4 * j + 3] = v.w;
                }
            } else {
#pragma unroll
                for (int j = 0; j < TN; j++) b[j] = Bs[k][tx * TN + j];
            }
#pragma unroll
            for (int i = 0; i < TM; i++)
#pragma unroll
                for (int j = 0; j < TN; j++) acc[i][j] = fmaf(a[i], b[j], acc[i][j]);
        }
        __syncthreads();
    }

#pragma unroll
    for (int i = 0; i < TM; i++) {
        size_t gm = (size_t)(m0 + ty * TM + i);
#pragma unroll
        for (int j = 0; j < TN; j++) {
            int gn = n0 + tx * TN + j;
            if (gn < N) {
                float v = acc[i][j] + __ldg(bias + gn);
                if (RELU) v = fmaxf(v, 0.f);
                C[gm * N + gn] = v;
            }
        }
    }
}

// ---------------- launch ----------------
extern "C" void kernel_launch(void* const* d_in, const int* in_sizes, int n_in,
                              void* d_out, int out_size) {
    const float* x   = (const float*)d_in[0];
    const int*   ei  = (const int*)d_in[1];
    const float* ea  = (const float*)d_in[2];
    const float* Wg1 = (const float*)d_in[4];
    const float* as1 = (const float*)d_in[5];
    const float* ad1 = (const float*)d_in[6];
    const float* We1 = (const float*)d_in[7];
    const float* ae1 = (const float*)d_in[8];
    const float* bg1 = (const float*)d_in[9];
    const float* Wg2 = (const float*)d_in[10];
    const float* as2 = (const float*)d_in[11];
    const float* ad2 = (const float*)d_in[12];
    const float* We2 = (const float*)d_in[13];
    const float* ae2 = (const float*)d_in[14];
    const float* bg2 = (const float*)d_in[15];
    const float* W2  = (const float*)d_in[16];
    const float* b2  = (const float*)d_in[17];
    const float* We0 = (const float*)d_in[18];
    const float* be0 = (const float*)d_in[19];
    const float* W3  = (const float*)d_in[20];
    const float* b3  = (const float*)d_in[21];
    const float* Wm0 = (const float*)d_in[22];
    const float* bm0 = (const float*)d_in[23];
    const float* Wm1 = (const float*)d_in[24];
    const float* bm1 = (const float*)d_in[25];
    const float* Wm2 = (const float*)d_in[26];
    const float* bm2 = (const float*)d_in[27];
    const float* W4  = (const float*)d_in[28];
    const float* b4  = (const float*)d_in[29];
    float* out = (float*)d_out;

    float *p_h, *p_s, *p_d, *p_y0, *p_y1, *p_y4, *p_A, *p_B;
    cudaGetSymbolAddress((void**)&p_h, g_h);
    cudaGetSymbolAddress((void**)&p_s, g_s);
    cudaGetSymbolAddress((void**)&p_d, g_d);
    cudaGetSymbolAddress((void**)&p_y0, g_y0);
    cudaGetSymbolAddress((void**)&p_y1, g_y1);
    cudaGetSymbolAddress((void**)&p_y4, g_y4);
    cudaGetSymbolAddress((void**)&p_A, g_bufA);
    cudaGetSymbolAddress((void**)&p_B, g_bufB);

    const int initGrid = (NNODES * HID + 255) / 256;
    const int nodeGrid = (NNODES + 127) / 128;
    const int edgeGrid = (NEDGES + 255) / 256;
    const int aggGrid  = (int)(((long long)NEDGES * HID) / 256);

    k_prep_we<<<1, 32>>>(We1, ae1, We2, ae2);

    // ---- GAT layer 1 ----
    k_init<<<initGrid, 256>>>();
    k_node_gemm<128, 0><<<nodeGrid, 128>>>(x, nullptr, Wg1, as1, ad1, p_h, p_s, p_d);
    k_edge_logit<<<edgeGrid, 256>>>(ei, ea, 0);
    k_edge_exp_agg<<<aggGrid, 256>>>(ei);
    k_node_fin<<<initGrid, 256>>>(bg1, p_y0);

    // ---- GAT layer 2 ----
    k_init<<<initGrid, 256>>>();
    k_node_gemm<64, 0><<<nodeGrid, 128>>>(p_y0, nullptr, Wg2, as2, ad2, p_h, p_s, p_d);
    k_edge_logit<<<edgeGrid, 256>>>(ei, ea, 1);
    k_edge_exp_agg<<<aggGrid, 256>>>(ei);
    k_node_fin<<<initGrid, 256>>>(bg2, p_y1);

    // ---- l2: y4 = relu((y0+y1) @ W2 + b2) ----
    k_node_gemm<64, 1><<<nodeGrid, 128>>>(p_y0, p_y1, W2, b2, nullptr, p_y4, nullptr, nullptr);

    // ---- edge MLP ----
    k_build_xb<<<NEDGES, 128>>>(ei, ea, We0, be0, p_y4, p_A);

    dim3 gh(NEDGES / 128, 1);
    k_gemm<128, 128, 16, 8, 8, true><<<gh, 256>>>(p_A, W3, b3, p_B, NEDGES, 128, 128);
    k_gemm<128, 128, 16, 8, 8, true><<<gh, 256>>>(p_B, Wm0, bm0, p_A, NEDGES, 128, 128);
    k_gemm<128, 128, 16, 8, 8, true><<<gh, 256>>>(p_A, Wm1, bm1, p_B, NEDGES, 128, 128);
    k_gemm<128, 128, 16, 8, 8, true><<<gh, 256>>>(p_B, Wm2, bm2, p_A, NEDGES, 128, 128);

    dim3 gf(NEDGES / 128, 2);  // BN=80 covers 145 output cols in 2 column blocks
    k_gemm<128, 80, 16, 8, 5, false><<<gf, 256>>>(p_A, W4, b4, out, NEDGES, 145, 128);
}

// round 8
// speedup vs baseline: 2.1427x; 2.1427x over previous
#include <cuda_runtime.h>
#include <cuda_bf16.h>
#include <cstdint>

#define NNODES 50000
#define NEDGES 800000
#define HID 64

// ---------------- scratch (static device globals; no allocation) ----------------
__device__ float    g_h[NNODES * HID];
__device__ float    g_s[NNODES];
__device__ float    g_d[NNODES];
__device__ unsigned g_menc[NNODES];
__device__ float    g_den[NNODES];
__device__ float    g_agg[NNODES * HID];
__device__ float    g_y0[NNODES * HID];
__device__ float    g_y1[NNODES * HID];
__device__ float    g_y4[NNODES * HID];
__device__ float    g_logit[NEDGES];
__device__ float    g_bufA[(size_t)NEDGES * 128];
__device__ float    g_bufB[(size_t)NEDGES * 128];
__device__ float    g_we[4];
// B fragments in mma register order: layers 0-3 (NT=16): 16384 u32 each; layer 4 (NT=20): 20480
__device__ uint32_t g_Bfrag[4 * 16384 + 20480];

// ---------------- misc helpers ----------------
__device__ __forceinline__ unsigned ord_enc(float f) {
    unsigned u = __float_as_uint(f);
    return (u & 0x80000000u) ? ~u : (u | 0x80000000u);
}
__device__ __forceinline__ float ord_dec(unsigned u) {
    return (u & 0x80000000u) ? __uint_as_float(u ^ 0x80000000u) : __uint_as_float(~u);
}

__device__ __forceinline__ void mma_bf16(float* c, const uint32_t* a, const uint32_t* b) {
    asm volatile(
        "mma.sync.aligned.m16n8k16.row.col.f32.bf16.bf16.f32 "
        "{%0,%1,%2,%3}, {%4,%5,%6,%7}, {%8,%9}, {%0,%1,%2,%3};"
        : "+f"(c[0]), "+f"(c[1]), "+f"(c[2]), "+f"(c[3])
        : "r"(a[0]), "r"(a[1]), "r"(a[2]), "r"(a[3]), "r"(b[0]), "r"(b[1]));
}

// ---------------- tiny prep: w = We @ ae for both GAT layers ----------------
__global__ void k_prep_we(const float* __restrict__ We1, const float* __restrict__ ae1,
                          const float* __restrict__ We2, const float* __restrict__ ae2) {
    int t = threadIdx.x;
    if (t < 4) {
        const float* W = (t < 2) ? We1 : We2;
        const float* a = (t < 2) ? ae1 : ae2;
        int r = t & 1;
        float s = 0.f;
        for (int j = 0; j < HID; j++) s += W[r * HID + j] * a[j];
        g_we[t] = s;
    }
}

// ---------------- B fragment prep: W[128,Nreal] fp32 -> hi/lo bf16 mma fragments ----
// Fragment layout: idx = ((kt*NT + nt)*32 + lane); 4 u32 per idx: {hi0, hi1, lo0, lo1}.
// b0 pair = B[k0, n],B[k0+1, n]; b1 pair = B[k0+8, n],B[k0+9, n];
// k0 = kt*16 + t*2, n = nt*8 + g, with g=lane>>2, t=lane&3.
__global__ void k_prep_bfrag(const float* __restrict__ W, int Nreal, int NT,
                             uint32_t* __restrict__ out) {
    int idx = blockIdx.x * blockDim.x + threadIdx.x;
    if (idx >= 8 * NT * 32) return;
    int lane = idx & 31;
    int nt = (idx >> 5) % NT;
    int kt = idx / (NT * 32);
    int g = lane >> 2, t = lane & 3;
    int n = nt * 8 + g;
    int k0 = kt * 16 + t * 2;
    float w0 = (n < Nreal) ? __ldg(W + (k0 + 0) * Nreal + n) : 0.f;
    float w1 = (n < Nreal) ? __ldg(W + (k0 + 1) * Nreal + n) : 0.f;
    float w2 = (n < Nreal) ? __ldg(W + (k0 + 8) * Nreal + n) : 0.f;
    float w3 = (n < Nreal) ? __ldg(W + (k0 + 9) * Nreal + n) : 0.f;
    __nv_bfloat162 h0 = __floats2bfloat162_rn(w0, w1);
    __nv_bfloat162 h1 = __floats2bfloat162_rn(w2, w3);
    float2 f0 = __bfloat1622float2(h0);
    float2 f1 = __bfloat1622float2(h1);
    __nv_bfloat162 l0 = __floats2bfloat162_rn(w0 - f0.x, w1 - f0.y);
    __nv_bfloat162 l1 = __floats2bfloat162_rn(w2 - f1.x, w3 - f1.y);
    uint32_t* o = out + (size_t)idx * 4;
    o[0] = *reinterpret_cast<uint32_t*>(&h0);
    o[1] = *reinterpret_cast<uint32_t*>(&h1);
    o[2] = *reinterpret_cast<uint32_t*>(&l0);
    o[3] = *reinterpret_cast<uint32_t*>(&l1);
}

// ---------------- per-call re-init of aggregation scratch ----------------
__global__ void k_init() {
    int gid = blockIdx.x * blockDim.x + threadIdx.x;
    if (gid < NNODES * HID) g_agg[gid] = 0.f;
    if (gid < NNODES) { g_den[gid] = 0.f; g_menc[gid] = 0x007fffffu; /* enc(-inf) */ }
}

// ---------------- node GEMM (small, stays fp32 scalar) ----------------
template <int K, int MODE>
__global__ __launch_bounds__(128) void k_node_gemm(
    const float* __restrict__ X, const float* __restrict__ X2,
    const float* __restrict__ W, const float* __restrict__ v1,
    const float* __restrict__ v2,
    float* __restrict__ H, float* __restrict__ S, float* __restrict__ D) {
    __shared__ float Ws[K * HID];
    __shared__ float sv1[HID], sv2[HID];
    int tid = threadIdx.x;
    for (int i = tid; i < K * HID; i += 128) Ws[i] = W[i];
    if (tid < HID) {
        sv1[tid] = v1 ? v1[tid] : 0.f;
        sv2[tid] = v2 ? v2[tid] : 0.f;
    }
    __syncthreads();
    int node = blockIdx.x * 128 + tid;
    if (node >= NNODES) return;

    float acc[HID];
#pragma unroll
    for (int n = 0; n < HID; n++) acc[n] = 0.f;

    const float4* xr = reinterpret_cast<const float4*>(X + (size_t)node * K);
    const float4* xr2 = (MODE == 1) ? reinterpret_cast<const float4*>(X2 + (size_t)node * K) : nullptr;
#pragma unroll 1
    for (int k4 = 0; k4 < K / 4; k4++) {
        float4 v = __ldg(xr + k4);
        if (MODE == 1) {
            float4 w = __ldg(xr2 + k4);
            v.x += w.x; v.y += w.y; v.z += w.z; v.w += w.w;
        }
        float xv[4] = {v.x, v.y, v.z, v.w};
#pragma unroll
        for (int kk = 0; kk < 4; kk++) {
            const float* wr = &Ws[(k4 * 4 + kk) * HID];
#pragma unroll
            for (int n = 0; n < HID; n++) acc[n] = fmaf(xv[kk], wr[n], acc[n]);
        }
    }

    if (MODE == 0) {
        float s = 0.f, d = 0.f;
#pragma unroll
        for (int n = 0; n < HID; n++) { s += acc[n] * sv1[n]; d += acc[n] * sv2[n]; }
        S[node] = s;
        D[node] = d;
    } else {
#pragma unroll
        for (int n = 0; n < HID; n++) acc[n] = fmaxf(acc[n] + sv1[n], 0.f);
    }
    float4* hr = reinterpret_cast<float4*>(H + (size_t)node * HID);
#pragma unroll
    for (int i = 0; i < HID / 4; i++)
        hr[i] = make_float4(acc[4 * i], acc[4 * i + 1], acc[4 * i + 2], acc[4 * i + 3]);
}

// ---------------- edge logit + segment max ----------------
__global__ void k_edge_logit(const int* __restrict__ EI, const float* __restrict__ EA, int which) {
    int e = blockIdx.x * blockDim.x + threadIdx.x;
    if (e >= NEDGES) return;
    int src = __ldg(EI + e);
    int dst = __ldg(EI + NEDGES + e);
    float w0 = g_we[which * 2], w1 = g_we[which * 2 + 1];
    float lg = __ldg(&g_s[src]) + __ldg(&g_d[dst]) + __ldg(EA + 2 * e) * w0 + __ldg(EA + 2 * e + 1) * w1;
    lg = (lg > 0.f) ? lg : 0.2f * lg;
    g_logit[e] = lg;
    atomicMax(&g_menc[dst], ord_enc(lg));
}

// ---------------- edge exp + den + unnormalized aggregation ----------------
__global__ void k_edge_exp_agg(const int* __restrict__ EI) {
    long long gid = (long long)blockIdx.x * blockDim.x + threadIdx.x;
    int e = (int)(gid >> 6);
    int n = (int)(gid & 63);
    if (e >= NEDGES) return;
    int src = __ldg(EI + e);
    int dst = __ldg(EI + NEDGES + e);
    float m = ord_dec(g_menc[dst]);
    float ex = expf(g_logit[e] - m);
    float val = ex * __ldg(&g_h[(size_t)src * HID + n]);
    atomicAdd(&g_agg[(size_t)dst * HID + n], val);
    if (n == 0) atomicAdd(&g_den[dst], ex);
}

// ---------------- normalize + bias + relu ----------------
__global__ void k_node_fin(const float* __restrict__ bias, float* __restrict__ Y) {
    int gid = blockIdx.x * blockDim.x + threadIdx.x;
    if (gid >= NNODES * HID) return;
    int n = gid & 63;
    float den = fmaxf(g_den[gid >> 6], 1e-16f);
    Y[gid] = fmaxf(g_agg[gid] / den + __ldg(bias + n), 0.f);
}

// ---------------- build concat([y4[src]+y4[dst], relu(ea@We0+be0)]) ----------------
__global__ __launch_bounds__(128) void k_build_xb(
    const int* __restrict__ EI, const float* __restrict__ EA,
    const float* __restrict__ We0, const float* __restrict__ be0,
    const float* __restrict__ Y4, float* __restrict__ XB) {
    int e = blockIdx.x;
    int c = threadIdx.x;
    int src = __ldg(EI + e);
    int dst = __ldg(EI + NEDGES + e);
    float v;
    if (c < HID) {
        v = __ldg(&Y4[(size_t)src * HID + c]) + __ldg(&Y4[(size_t)dst * HID + c]);
    } else {
        int c2 = c - HID;
        v = fmaxf(__ldg(EA + 2 * e) * __ldg(We0 + c2) + __ldg(EA + 2 * e + 1) * __ldg(We0 + HID + c2)
                      + __ldg(be0 + c2),
                  0.f);
    }
    XB[(size_t)e * 128 + c] = v;
}

// ================= bf16-split tensor-core GEMM via mma.sync (portable HMMA) ========
// C[M,NOUT] = act(A[M,128] @ W + bias). A fp32 row-major; W pre-shuffled fragments.
// CTA: 128 rows x (NT*8) cols, 256 threads = 8 warps (2 m x 4 n), warp tile 64 x NTW*8.
// NT = 4*NTW so the 4-wide warp grid covers all columns.
// SMEM: A tile as hi/lo bf16, row stride 272 B (conflict-free), 2 x 34816 B.
template <int NT, int NTW, bool RELU, int NOUT>
__global__ __launch_bounds__(256) void k_hgemm(
    const float* __restrict__ A, const uint32_t* __restrict__ Bfrag,
    const float* __restrict__ bias, float* __restrict__ C) {
    static_assert(NT == 4 * NTW, "warp grid must cover all column tiles");
    extern __shared__ char sm[];
    const int tid = threadIdx.x;
    const int wid = tid >> 5, lane = tid & 31;
    const int g = lane >> 2, t = lane & 3;
    const int wm = wid >> 2, wn = wid & 3;  // 2 (m) x 4 (n)
    const int m0 = blockIdx.x * 128;

    // ---- stage A tile: fp32 -> (hi, lo) bf16, row-major stride 272 B ----
    {
        const float4* Ag = reinterpret_cast<const float4*>(A + (size_t)m0 * 128);
#pragma unroll
        for (int it = 0; it < 16; it++) {
            int i = tid + it * 256;
            int row = i >> 5, col = (i & 31) * 4;
            float4 v = __ldg(Ag + i);
            __nv_bfloat162 h0 = __floats2bfloat162_rn(v.x, v.y);
            __nv_bfloat162 h1 = __floats2bfloat162_rn(v.z, v.w);
            float2 f0 = __bfloat1622float2(h0);
            float2 f1 = __bfloat1622float2(h1);
            __nv_bfloat162 l0 = __floats2bfloat162_rn(v.x - f0.x, v.y - f0.y);
            __nv_bfloat162 l1 = __floats2bfloat162_rn(v.z - f1.x, v.w - f1.y);
            char* p = sm + row * 272 + col * 2;
            *reinterpret_cast<uint2*>(p) =
                make_uint2(*reinterpret_cast<uint32_t*>(&h0), *reinterpret_cast<uint32_t*>(&h1));
            *reinterpret_cast<uint2*>(p + 34816) =
                make_uint2(*reinterpret_cast<uint32_t*>(&l0), *reinterpret_cast<uint32_t*>(&l1));
        }
    }
    __syncthreads();

    float acc[4][NTW][4];
#pragma unroll
    for (int a = 0; a < 4; a++)
#pragma unroll
        for (int b = 0; b < NTW; b++)
#pragma unroll
            for (int c = 0; c < 4; c++) acc[a][b][c] = 0.f;

#pragma unroll 1
    for (int kt = 0; kt < 8; kt++) {
        uint32_t bh[NTW][2], bl[NTW][2];
        const uint32_t* bp = Bfrag + ((size_t)(kt * NT + wn * NTW) * 32 + lane) * 4;
#pragma unroll
        for (int nt = 0; nt < NTW; nt++) {
            bh[nt][0] = __ldg(bp + nt * 128 + 0);
            bh[nt][1] = __ldg(bp + nt * 128 + 1);
            bl[nt][0] = __ldg(bp + nt * 128 + 2);
            bl[nt][1] = __ldg(bp + nt * 128 + 3);
        }
#pragma unroll
        for (int mt = 0; mt < 4; mt++) {
            const char* Ah = sm + (wm * 64 + mt * 16 + g) * 272 + (kt * 16 + t * 2) * 2;
            uint32_t ah[4], al[4];
            ah[0] = *reinterpret_cast<const uint32_t*>(Ah);
            ah[1] = *reinterpret_cast<const uint32_t*>(Ah + 8 * 272);
            ah[2] = *reinterpret_cast<const uint32_t*>(Ah + 16);
            ah[3] = *reinterpret_cast<const uint32_t*>(Ah + 8 * 272 + 16);
            al[0] = *reinterpret_cast<const uint32_t*>(Ah + 34816);
            al[1] = *reinterpret_cast<const uint32_t*>(Ah + 34816 + 8 * 272);
            al[2] = *reinterpret_cast<const uint32_t*>(Ah + 34816 + 16);
            al[3] = *reinterpret_cast<const uint32_t*>(Ah + 34816 + 8 * 272 + 16);
#pragma unroll
            for (int nt = 0; nt < NTW; nt++) {
                mma_bf16(acc[mt][nt], ah, bh[nt]);
                mma_bf16(acc[mt][nt], ah, bl[nt]);
                mma_bf16(acc[mt][nt], al, bh[nt]);
            }
        }
    }

    // ---- epilogue: bias + act + store ----
#pragma unroll
    for (int mt = 0; mt < 4; mt++) {
        const int r0 = m0 + wm * 64 + mt * 16 + g;
#pragma unroll
        for (int nt = 0; nt < NTW; nt++) {
            const int c0 = wn * NTW * 8 + nt * 8 + t * 2;
            float bv0 = (c0 < NOUT) ? __ldg(bias + c0) : 0.f;
            float bv1 = (c0 + 1 < NOUT) ? __ldg(bias + c0 + 1) : 0.f;
            float v0 = acc[mt][nt][0] + bv0;
            float v1 = acc[mt][nt][1] + bv1;
            float v2 = acc[mt][nt][2] + bv0;
            float v3 = acc[mt][nt][3] + bv1;
            if (RELU) {
                v0 = fmaxf(v0, 0.f); v1 = fmaxf(v1, 0.f);
                v2 = fmaxf(v2, 0.f); v3 = fmaxf(v3, 0.f);
            }
            if constexpr (NOUT % 2 == 0) {
                *reinterpret_cast<float2*>(C + (size_t)r0 * NOUT + c0) = make_float2(v0, v1);
                *reinterpret_cast<float2*>(C + (size_t)(r0 + 8) * NOUT + c0) = make_float2(v2, v3);
            } else {
                if (c0 < NOUT) {
                    C[(size_t)r0 * NOUT + c0] = v0;
                    C[(size_t)(r0 + 8) * NOUT + c0] = v2;
                }
                if (c0 + 1 < NOUT) {
                    C[(size_t)r0 * NOUT + c0 + 1] = v1;
                    C[(size_t)(r0 + 8) * NOUT + c0 + 1] = v3;
                }
            }
        }
    }
}

// ---------------- launch ----------------
extern "C" void kernel_launch(void* const* d_in, const int* in_sizes, int n_in,
                              void* d_out, int out_size) {
    const float* x   = (const float*)d_in[0];
    const int*   ei  = (const int*)d_in[1];
    const float* ea  = (const float*)d_in[2];
    const float* Wg1 = (const float*)d_in[4];
    const float* as1 = (const float*)d_in[5];
    const float* ad1 = (const float*)d_in[6];
    const float* We1 = (const float*)d_in[7];
    const float* ae1 = (const float*)d_in[8];
    const float* bg1 = (const float*)d_in[9];
    const float* Wg2 = (const float*)d_in[10];
    const float* as2 = (const float*)d_in[11];
    const float* ad2 = (const float*)d_in[12];
    const float* We2 = (const float*)d_in[13];
    const float* ae2 = (const float*)d_in[14];
    const float* bg2 = (const float*)d_in[15];
    const float* W2  = (const float*)d_in[16];
    const float* b2  = (const float*)d_in[17];
    const float* We0 = (const float*)d_in[18];
    const float* be0 = (const float*)d_in[19];
    const float* W3  = (const float*)d_in[20];
    const float* b3  = (const float*)d_in[21];
    const float* Wm0 = (const float*)d_in[22];
    const float* bm0 = (const float*)d_in[23];
    const float* Wm1 = (const float*)d_in[24];
    const float* bm1 = (const float*)d_in[25];
    const float* Wm2 = (const float*)d_in[26];
    const float* bm2 = (const float*)d_in[27];
    const float* W4  = (const float*)d_in[28];
    const float* b4  = (const float*)d_in[29];
    float* out = (float*)d_out;

    float *p_h, *p_s, *p_d, *p_y0, *p_y1, *p_y4, *p_A, *p_B;
    uint32_t* p_BF;
    cudaGetSymbolAddress((void**)&p_h, g_h);
    cudaGetSymbolAddress((void**)&p_s, g_s);
    cudaGetSymbolAddress((void**)&p_d, g_d);
    cudaGetSymbolAddress((void**)&p_y0, g_y0);
    cudaGetSymbolAddress((void**)&p_y1, g_y1);
    cudaGetSymbolAddress((void**)&p_y4, g_y4);
    cudaGetSymbolAddress((void**)&p_A, g_bufA);
    cudaGetSymbolAddress((void**)&p_B, g_bufB);
    cudaGetSymbolAddress((void**)&p_BF, g_Bfrag);

    const int SMA = 2 * 34816;  // 69632 B dynamic smem
    cudaFuncSetAttribute(k_hgemm<16, 4, true, 128>, cudaFuncAttributeMaxDynamicSharedMemorySize, SMA);
    cudaFuncSetAttribute(k_hgemm<20, 5, false, 145>, cudaFuncAttributeMaxDynamicSharedMemorySize, SMA);

    const int initGrid = (NNODES * HID + 255) / 256;
    const int nodeGrid = (NNODES + 127) / 128;
    const int edgeGrid = (NEDGES + 255) / 256;
    const int aggGrid  = (int)(((long long)NEDGES * HID) / 256);

    k_prep_we<<<1, 32>>>(We1, ae1, We2, ae2);

    // B fragments for the 5 tensor GEMMs
    k_prep_bfrag<<<(8 * 16 * 32 + 255) / 256, 256>>>(W3,  128, 16, p_BF + 0 * 16384);
    k_prep_bfrag<<<(8 * 16 * 32 + 255) / 256, 256>>>(Wm0, 128, 16, p_BF + 1 * 16384);
    k_prep_bfrag<<<(8 * 16 * 32 + 255) / 256, 256>>>(Wm1, 128, 16, p_BF + 2 * 16384);
    k_prep_bfrag<<<(8 * 16 * 32 + 255) / 256, 256>>>(Wm2, 128, 16, p_BF + 3 * 16384);
    k_prep_bfrag<<<(8 * 20 * 32 + 255) / 256, 256>>>(W4,  145, 20, p_BF + 4 * 16384);

    // ---- GAT layer 1 ----
    k_init<<<initGrid, 256>>>();
    k_node_gemm<128, 0><<<nodeGrid, 128>>>(x, nullptr, Wg1, as1, ad1, p_h, p_s, p_d);
    k_edge_logit<<<edgeGrid, 256>>>(ei, ea, 0);
    k_edge_exp_agg<<<aggGrid, 256>>>(ei);
    k_node_fin<<<initGrid, 256>>>(bg1, p_y0);

    // ---- GAT layer 2 ----
    k_init<<<initGrid, 256>>>();
    k_node_gemm<64, 0><<<nodeGrid, 128>>>(p_y0, nullptr, Wg2, as2, ad2, p_h, p_s, p_d);
    k_edge_logit<<<edgeGrid, 256>>>(ei, ea, 1);
    k_edge_exp_agg<<<aggGrid, 256>>>(ei);
    k_node_fin<<<initGrid, 256>>>(bg2, p_y1);

    // ---- l2: y4 = relu((y0+y1) @ W2 + b2) ----
    k_node_gemm<64, 1><<<nodeGrid, 128>>>(p_y0, p_y1, W2, b2, nullptr, p_y4, nullptr, nullptr);

    // ---- edge MLP (bf16-split HMMA GEMMs) ----
    k_build_xb<<<NEDGES, 128>>>(ei, ea, We0, be0, p_y4, p_A);

    const int GT = NEDGES / 128;  // 6250
    k_hgemm<16, 4, true, 128><<<GT, 256, SMA>>>(p_A, p_BF + 0 * 16384, b3,  p_B);
    k_hgemm<16, 4, true, 128><<<GT, 256, SMA>>>(p_B, p_BF + 1 * 16384, bm0, p_A);
    k_hgemm<16, 4, true, 128><<<GT, 256, SMA>>>(p_A, p_BF + 2 * 16384, bm1, p_B);
    k_hgemm<16, 4, true, 128><<<GT, 256, SMA>>>(p_B, p_BF + 3 * 16384, bm2, p_A);
    k_hgemm<20, 5, false, 145><<<GT, 256, SMA>>>(p_A, p_BF + 4 * 16384, b4, out);
}

// round 9
// speedup vs baseline: 3.2439x; 1.5139x over previous
#include <cuda_runtime.h>
#include <cuda_bf16.h>
#include <cstdint>

#define NNODES 50000
#define NEDGES 800000
#define HID 64

// ---------------- scratch (static device globals; no allocation) ----------------
__device__ float    g_h[NNODES * HID];
__device__ float    g_s[NNODES];
__device__ float    g_d[NNODES];
__device__ float    g_den[NNODES];
__device__ float    g_agg[NNODES * HID];
__device__ float    g_y0[NNODES * HID];
__device__ float    g_y1[NNODES * HID];
__device__ float    g_y4[NNODES * HID];
__device__ float    g_we[4];
// B fragments in mma register order: layers 0-3 (NT=16): 16384 u32 each; layer 4 (NT=20): 20480
__device__ uint32_t g_Bfrag[4 * 16384 + 20480];

__device__ __forceinline__ void mma_bf16(float* c, const uint32_t* a, const uint32_t* b) {
    asm volatile(
        "mma.sync.aligned.m16n8k16.row.col.f32.bf16.bf16.f32 "
        "{%0,%1,%2,%3}, {%4,%5,%6,%7}, {%8,%9}, {%0,%1,%2,%3};"
        : "+f"(c[0]), "+f"(c[1]), "+f"(c[2]), "+f"(c[3])
        : "r"(a[0]), "r"(a[1]), "r"(a[2]), "r"(a[3]), "r"(b[0]), "r"(b[1]));
}

// ---------------- tiny prep: w = We @ ae for both GAT layers ----------------
__global__ void k_prep_we(const float* __restrict__ We1, const float* __restrict__ ae1,
                          const float* __restrict__ We2, const float* __restrict__ ae2) {
    int t = threadIdx.x;
    if (t < 4) {
        const float* W = (t < 2) ? We1 : We2;
        const float* a = (t < 2) ? ae1 : ae2;
        int r = t & 1;
        float s = 0.f;
        for (int j = 0; j < HID; j++) s += W[r * HID + j] * a[j];
        g_we[t] = s;
    }
}

// ---------------- B fragment prep: W[128,Nreal] fp32 -> hi/lo bf16 mma fragments ----
__global__ void k_prep_bfrag(const float* __restrict__ W, int Nreal, int NT,
                             uint32_t* __restrict__ out) {
    int idx = blockIdx.x * blockDim.x + threadIdx.x;
    if (idx >= 8 * NT * 32) return;
    int lane = idx & 31;
    int nt = (idx >> 5) % NT;
    int kt = idx / (NT * 32);
    int g = lane >> 2, t = lane & 3;
    int n = nt * 8 + g;
    int k0 = kt * 16 + t * 2;
    float w0 = (n < Nreal) ? __ldg(W + (k0 + 0) * Nreal + n) : 0.f;
    float w1 = (n < Nreal) ? __ldg(W + (k0 + 1) * Nreal + n) : 0.f;
    float w2 = (n < Nreal) ? __ldg(W + (k0 + 8) * Nreal + n) : 0.f;
    float w3 = (n < Nreal) ? __ldg(W + (k0 + 9) * Nreal + n) : 0.f;
    __nv_bfloat162 h0 = __floats2bfloat162_rn(w0, w1);
    __nv_bfloat162 h1 = __floats2bfloat162_rn(w2, w3);
    float2 f0 = __bfloat1622float2(h0);
    float2 f1 = __bfloat1622float2(h1);
    __nv_bfloat162 l0 = __floats2bfloat162_rn(w0 - f0.x, w1 - f0.y);
    __nv_bfloat162 l1 = __floats2bfloat162_rn(w2 - f1.x, w3 - f1.y);
    uint32_t* o = out + (size_t)idx * 4;
    o[0] = *reinterpret_cast<uint32_t*>(&h0);
    o[1] = *reinterpret_cast<uint32_t*>(&h1);
    o[2] = *reinterpret_cast<uint32_t*>(&l0);
    o[3] = *reinterpret_cast<uint32_t*>(&l1);
}

// ---------------- per-call re-init of aggregation scratch ----------------
__global__ void k_init() {
    int gid = blockIdx.x * blockDim.x + threadIdx.x;
    if (gid < NNODES * HID) g_agg[gid] = 0.f;
    if (gid < NNODES) g_den[gid] = 0.f;
}

// ---------------- node GEMM (small, stays fp32 scalar) ----------------
template <int K, int MODE>
__global__ __launch_bounds__(128) void k_node_gemm(
    const float* __restrict__ X, const float* __restrict__ X2,
    const float* __restrict__ W, const float* __restrict__ v1,
    const float* __restrict__ v2,
    float* __restrict__ H, float* __restrict__ S, float* __restrict__ D) {
    __shared__ float Ws[K * HID];
    __shared__ float sv1[HID], sv2[HID];
    int tid = threadIdx.x;
    for (int i = tid; i < K * HID; i += 128) Ws[i] = W[i];
    if (tid < HID) {
        sv1[tid] = v1 ? v1[tid] : 0.f;
        sv2[tid] = v2 ? v2[tid] : 0.f;
    }
    __syncthreads();
    int node = blockIdx.x * 128 + tid;
    if (node >= NNODES) return;

    float acc[HID];
#pragma unroll
    for (int n = 0; n < HID; n++) acc[n] = 0.f;

    const float4* xr = reinterpret_cast<const float4*>(X + (size_t)node * K);
    const float4* xr2 = (MODE == 1) ? reinterpret_cast<const float4*>(X2 + (size_t)node * K) : nullptr;
#pragma unroll 1
    for (int k4 = 0; k4 < K / 4; k4++) {
        float4 v = __ldg(xr + k4);
        if (MODE == 1) {
            float4 w = __ldg(xr2 + k4);
            v.x += w.x; v.y += w.y; v.z += w.z; v.w += w.w;
        }
        float xv[4] = {v.x, v.y, v.z, v.w};
#pragma unroll
        for (int kk = 0; kk < 4; kk++) {
            const float* wr = &Ws[(k4 * 4 + kk) * HID];
#pragma unroll
            for (int n = 0; n < HID; n++) acc[n] = fmaf(xv[kk], wr[n], acc[n]);
        }
    }

    if (MODE == 0) {
        float s = 0.f, d = 0.f;
#pragma unroll
        for (int n = 0; n < HID; n++) { s += acc[n] * sv1[n]; d += acc[n] * sv2[n]; }
        S[node] = s;
        D[node] = d;
    } else {
#pragma unroll
        for (int n = 0; n < HID; n++) acc[n] = fmaxf(acc[n] + sv1[n], 0.f);
    }
    float4* hr = reinterpret_cast<float4*>(H + (size_t)node * HID);
#pragma unroll
    for (int i = 0; i < HID / 4; i++)
        hr[i] = make_float4(acc[4 * i], acc[4 * i + 1], acc[4 * i + 2], acc[4 * i + 3]);
}

// ---------------- fused edge pass: logit + exp (no max; logits provably tiny) + agg -----
// 16 threads per edge; exp computed once per edge (lanes 0/16) and shuffled;
// channel aggregation via red.global.add.v4.f32 (sm_90+).
__global__ __launch_bounds__(256) void k_edge_agg(const int* __restrict__ EI,
                                                  const float* __restrict__ EA, int which) {
    int gid = blockIdx.x * blockDim.x + threadIdx.x;
    int e = gid >> 4;
    int q = gid & 15;
    if (e >= NEDGES) return;
    int lane = threadIdx.x & 31;
    int src = __ldg(EI + e);
    int dst = __ldg(EI + NEDGES + e);
    float ex = 0.f;
    if ((lane & 15) == 0) {
        float w0 = g_we[which * 2], w1 = g_we[which * 2 + 1];
        float lg = g_s[src] + g_d[dst] + __ldg(EA + 2 * e) * w0 + __ldg(EA + 2 * e + 1) * w1;
        lg = (lg > 0.f) ? lg : 0.2f * lg;  // leaky_relu 0.2
        ex = expf(lg);
        atomicAdd(&g_den[dst], ex);
    }
    ex = __shfl_sync(0xffffffffu, ex, lane & 16);
    float4 h4 = *reinterpret_cast<const float4*>(&g_h[(size_t)src * 64 + q * 4]);
    float vx = ex * h4.x, vy = ex * h4.y, vz = ex * h4.z, vw = ex * h4.w;
    asm volatile("red.global.add.v4.f32 [%0], {%1,%2,%3,%4};"
                 :: "l"(&g_agg[(size_t)dst * 64 + q * 4]),
                    "f"(vx), "f"(vy), "f"(vz), "f"(vw)
                 : "memory");
}

// ---------------- normalize + bias + relu ----------------
__global__ void k_node_fin(const float* __restrict__ bias, float* __restrict__ Y) {
    int gid = blockIdx.x * blockDim.x + threadIdx.x;
    if (gid >= NNODES * HID) return;
    int n = gid & 63;
    float den = fmaxf(g_den[gid >> 6], 1e-16f);
    Y[gid] = fmaxf(g_agg[gid] / den + __ldg(bias + n), 0.f);
}

// ================= fully fused edge MLP (gather + 5 bf16-split HMMA layers) =========
// SMEM map (dynamic, 77696 B):
//   [0, 34816)       A hi  (128 rows x 272 B stride)
//   [34816, 69632)   A lo
//   [0, 74240)       final fp32 staging (reuses A after last mainloop)
//   [74240, 77696)   consts: We0(128f) be0(64f) b0..b3(4x128f) b4(160f)
__device__ __forceinline__ void store_hilo2(char* p, float x, float y) {
    __nv_bfloat162 h = __floats2bfloat162_rn(x, y);
    float2 f = __bfloat1622float2(h);
    __nv_bfloat162 l = __floats2bfloat162_rn(x - f.x, y - f.y);
    *reinterpret_cast<uint32_t*>(p) = *reinterpret_cast<uint32_t*>(&h);
    *reinterpret_cast<uint32_t*>(p + 34816) = *reinterpret_cast<uint32_t*>(&l);
}

template <int NTW>
__device__ __forceinline__ void mlp_mainloop(
    const char* sm, const uint32_t* __restrict__ Bf,
    int wm, int wn, int lane, float (&acc)[4][NTW][4]) {
    constexpr int NT = 4 * NTW;
    const int g = lane >> 2, t = lane & 3;
#pragma unroll
    for (int a = 0; a < 4; a++)
#pragma unroll
        for (int b = 0; b < NTW; b++)
#pragma unroll
            for (int c = 0; c < 4; c++) acc[a][b][c] = 0.f;
#pragma unroll 1
    for (int kt = 0; kt < 8; kt++) {
        uint32_t bh[NTW][2], bl[NTW][2];
        const uint32_t* bp = Bf + ((size_t)(kt * NT + wn * NTW) * 32 + lane) * 4;
#pragma unroll
        for (int nt = 0; nt < NTW; nt++) {
            bh[nt][0] = __ldg(bp + nt * 128 + 0);
            bh[nt][1] = __ldg(bp + nt * 128 + 1);
            bl[nt][0] = __ldg(bp + nt * 128 + 2);
            bl[nt][1] = __ldg(bp + nt * 128 + 3);
        }
#pragma unroll
        for (int mt = 0; mt < 4; mt++) {
            const char* Ah = sm + (wm * 64 + mt * 16 + g) * 272 + (kt * 16 + t * 2) * 2;
            uint32_t ah[4], al[4];
            ah[0] = *reinterpret_cast<const uint32_t*>(Ah);
            ah[1] = *reinterpret_cast<const uint32_t*>(Ah + 8 * 272);
            ah[2] = *reinterpret_cast<const uint32_t*>(Ah + 16);
            ah[3] = *reinterpret_cast<const uint32_t*>(Ah + 8 * 272 + 16);
            al[0] = *reinterpret_cast<const uint32_t*>(Ah + 34816);
            al[1] = *reinterpret_cast<const uint32_t*>(Ah + 34816 + 8 * 272);
            al[2] = *reinterpret_cast<const uint32_t*>(Ah + 34816 + 16);
            al[3] = *reinterpret_cast<const uint32_t*>(Ah + 34816 + 8 * 272 + 16);
#pragma unroll
            for (int nt = 0; nt < NTW; nt++) {
                mma_bf16(acc[mt][nt], ah, bh[nt]);
                mma_bf16(acc[mt][nt], ah, bl[nt]);
                mma_bf16(acc[mt][nt], al, bh[nt]);
            }
        }
    }
}

__global__ __launch_bounds__(256) void k_mlp(
    const int* __restrict__ EI, const float* __restrict__ EA,
    const float* __restrict__ Y4, const uint32_t* __restrict__ Bf,
    const float* __restrict__ We0, const float* __restrict__ be0,
    const float* __restrict__ b3, const float* __restrict__ bm0,
    const float* __restrict__ bm1, const float* __restrict__ bm2,
    const float* __restrict__ b4, float* __restrict__ out) {
    extern __shared__ char sm[];
    float* cs = reinterpret_cast<float*>(sm + 74240);
    const int tid = threadIdx.x;
    const int wid = tid >> 5, lane = tid & 31;
    const int g = lane >> 2, t = lane & 3;
    const int wm = wid >> 2, wn = wid & 3;
    const int m0 = blockIdx.x * 128;

    // consts -> smem
    for (int i = tid; i < 128; i += 256) {
        cs[i] = __ldg(We0 + i);
        cs[192 + i] = __ldg(b3 + i);
        cs[320 + i] = __ldg(bm0 + i);
        cs[448 + i] = __ldg(bm1 + i);
        cs[576 + i] = __ldg(bm2 + i);
    }
    for (int i = tid; i < 64; i += 256) cs[128 + i] = __ldg(be0 + i);
    for (int i = tid; i < 160; i += 256) cs[704 + i] = (i < 145) ? __ldg(b4 + i) : 0.f;
    __syncthreads();

    // stage layer-0 input: [y4[src]+y4[dst] | relu(ea@We0+be0)] -> hi/lo bf16 SMEM
#pragma unroll
    for (int it = 0; it < 16; it++) {
        int i = tid + it * 256;
        int row = i >> 5, col = (i & 31) * 4;
        int e = m0 + row;
        float4 v;
        if (col < 64) {
            int s = __ldg(EI + e), d = __ldg(EI + NEDGES + e);
            float4 a = *reinterpret_cast<const float4*>(Y4 + (size_t)s * 64 + col);
            float4 b = *reinterpret_cast<const float4*>(Y4 + (size_t)d * 64 + col);
            v = make_float4(a.x + b.x, a.y + b.y, a.z + b.z, a.w + b.w);
        } else {
            int c2 = col - 64;
            float e0 = __ldg(EA + 2 * e), e1 = __ldg(EA + 2 * e + 1);
            v.x = fmaxf(e0 * cs[c2 + 0] + e1 * cs[64 + c2 + 0] + cs[128 + c2 + 0], 0.f);
            v.y = fmaxf(e0 * cs[c2 + 1] + e1 * cs[64 + c2 + 1] + cs[128 + c2 + 1], 0.f);
            v.z = fmaxf(e0 * cs[c2 + 2] + e1 * cs[64 + c2 + 2] + cs[128 + c2 + 2], 0.f);
            v.w = fmaxf(e0 * cs[c2 + 3] + e1 * cs[64 + c2 + 3] + cs[128 + c2 + 3], 0.f);
        }
        char* p = sm + row * 272 + col * 2;
        store_hilo2(p, v.x, v.y);
        store_hilo2(p + 4, v.z, v.w);
    }
    __syncthreads();

    // 4 hidden layers, resident in SMEM
#pragma unroll 1
    for (int l = 0; l < 4; l++) {
        float acc[4][4][4];
        mlp_mainloop<4>(sm, Bf + l * 16384, wm, wn, lane, acc);
        __syncthreads();  // all A reads done before overwrite
        const float* bs = cs + 192 + l * 128;
#pragma unroll
        for (int mt = 0; mt < 4; mt++) {
            int r0 = wm * 64 + mt * 16 + g;
#pragma unroll
            for (int nt = 0; nt < 4; nt++) {
                int c0 = wn * 32 + nt * 8 + t * 2;
                float bv0 = bs[c0], bv1 = bs[c0 + 1];
                char* p0 = sm + r0 * 272 + c0 * 2;
                store_hilo2(p0, fmaxf(acc[mt][nt][0] + bv0, 0.f),
                                fmaxf(acc[mt][nt][1] + bv1, 0.f));
                store_hilo2(p0 + 8 * 272, fmaxf(acc[mt][nt][2] + bv0, 0.f),
                                          fmaxf(acc[mt][nt][3] + bv1, 0.f));
            }
        }
        __syncthreads();
    }

    // final layer: 160 padded cols, 145 real
    {
        float acc[4][5][4];
        mlp_mainloop<5>(sm, Bf + 4 * 16384, wm, wn, lane, acc);
        __syncthreads();
        float* epi = reinterpret_cast<float*>(sm);
        const float* bs = cs + 704;
#pragma unroll
        for (int mt = 0; mt < 4; mt++) {
            int r0 = wm * 64 + mt * 16 + g;
#pragma unroll
            for (int nt = 0; nt < 5; nt++) {
                int c0 = wn * 40 + nt * 8 + t * 2;
                float bv0 = bs[c0], bv1 = bs[c0 + 1];
                if (c0 < 145) {
                    epi[r0 * 145 + c0] = acc[mt][nt][0] + bv0;
                    epi[(r0 + 8) * 145 + c0] = acc[mt][nt][2] + bv0;
                }
                if (c0 + 1 < 145) {
                    epi[r0 * 145 + c0 + 1] = acc[mt][nt][1] + bv1;
                    epi[(r0 + 8) * 145 + c0 + 1] = acc[mt][nt][3] + bv1;
                }
            }
        }
        __syncthreads();
        float* Co = out + (size_t)m0 * 145;
        for (int i = tid; i < 128 * 145; i += 256) Co[i] = epi[i];
    }
}

// ---------------- launch ----------------
extern "C" void kernel_launch(void* const* d_in, const int* in_sizes, int n_in,
                              void* d_out, int out_size) {
    const float* x   = (const float*)d_in[0];
    const int*   ei  = (const int*)d_in[1];
    const float* ea  = (const float*)d_in[2];
    const float* Wg1 = (const float*)d_in[4];
    const float* as1 = (const float*)d_in[5];
    const float* ad1 = (const float*)d_in[6];
    const float* We1 = (const float*)d_in[7];
    const float* ae1 = (const float*)d_in[8];
    const float* bg1 = (const float*)d_in[9];
    const float* Wg2 = (const float*)d_in[10];
    const float* as2 = (const float*)d_in[11];
    const float* ad2 = (const float*)d_in[12];
    const float* We2 = (const float*)d_in[13];
    const float* ae2 = (const float*)d_in[14];
    const float* bg2 = (const float*)d_in[15];
    const float* W2  = (const float*)d_in[16];
    const float* b2  = (const float*)d_in[17];
    const float* We0 = (const float*)d_in[18];
    const float* be0 = (const float*)d_in[19];
    const float* W3  = (const float*)d_in[20];
    const float* b3  = (const float*)d_in[21];
    const float* Wm0 = (const float*)d_in[22];
    const float* bm0 = (const float*)d_in[23];
    const float* Wm1 = (const float*)d_in[24];
    const float* bm1 = (const float*)d_in[25];
    const float* Wm2 = (const float*)d_in[26];
    const float* bm2 = (const float*)d_in[27];
    const float* W4  = (const float*)d_in[28];
    const float* b4  = (const float*)d_in[29];
    float* out = (float*)d_out;

    float *p_h, *p_s, *p_d, *p_y0, *p_y1, *p_y4;
    uint32_t* p_BF;
    cudaGetSymbolAddress((void**)&p_h, g_h);
    cudaGetSymbolAddress((void**)&p_s, g_s);
    cudaGetSymbolAddress((void**)&p_d, g_d);
    cudaGetSymbolAddress((void**)&p_y0, g_y0);
    cudaGetSymbolAddress((void**)&p_y1, g_y1);
    cudaGetSymbolAddress((void**)&p_y4, g_y4);
    cudaGetSymbolAddress((void**)&p_BF, g_Bfrag);

    const int SMM = 77696;  // dynamic smem for k_mlp
    cudaFuncSetAttribute(k_mlp, cudaFuncAttributeMaxDynamicSharedMemorySize, SMM);

    const int initGrid = (NNODES * HID + 255) / 256;
    const int nodeGrid = (NNODES + 127) / 128;
    const int aggGrid  = (NEDGES * 16) / 256;  // 50000

    k_prep_we<<<1, 32>>>(We1, ae1, We2, ae2);

    // B fragments for the 5 tensor GEMMs
    k_prep_bfrag<<<(8 * 16 * 32 + 255) / 256, 256>>>(W3,  128, 16, p_BF + 0 * 16384);
    k_prep_bfrag<<<(8 * 16 * 32 + 255) / 256, 256>>>(Wm0, 128, 16, p_BF + 1 * 16384);
    k_prep_bfrag<<<(8 * 16 * 32 + 255) / 256, 256>>>(Wm1, 128, 16, p_BF + 2 * 16384);
    k_prep_bfrag<<<(8 * 16 * 32 + 255) / 256, 256>>>(Wm2, 128, 16, p_BF + 3 * 16384);
    k_prep_bfrag<<<(8 * 20 * 32 + 255) / 256, 256>>>(W4,  145, 20, p_BF + 4 * 16384);

    // ---- GAT layer 1 ----
    k_init<<<initGrid, 256>>>();
    k_node_gemm<128, 0><<<nodeGrid, 128>>>(x, nullptr, Wg1, as1, ad1, p_h, p_s, p_d);
    k_edge_agg<<<aggGrid, 256>>>(ei, ea, 0);
    k_node_fin<<<initGrid, 256>>>(bg1, p_y0);

    // ---- GAT layer 2 ----
    k_init<<<initGrid, 256>>>();
    k_node_gemm<64, 0><<<nodeGrid, 128>>>(p_y0, nullptr, Wg2, as2, ad2, p_h, p_s, p_d);
    k_edge_agg<<<aggGrid, 256>>>(ei, ea, 1);
    k_node_fin<<<initGrid, 256>>>(bg2, p_y1);

    // ---- l2: y4 = relu((y0+y1) @ W2 + b2) ----
    k_node_gemm<64, 1><<<nodeGrid, 128>>>(p_y0, p_y1, W2, b2, nullptr, p_y4, nullptr, nullptr);

    // ---- fully fused edge MLP ----
    k_mlp<<<NEDGES / 128, 256, SMM>>>(ei, ea, p_y4, p_BF, We0, be0, b3, bm0, bm1, bm2, b4, out);
}

// round 10
// speedup vs baseline: 4.2143x; 1.2992x over previous
#include <cuda_runtime.h>
#include <cuda_fp16.h>
#include <cstdint>

#define NNODES 50000
#define NEDGES 800000
#define HID 64

// ---------------- scratch (static device globals; no allocation) ----------------
__device__ float    g_h[NNODES * HID];
__device__ float    g_s[NNODES];
__device__ float    g_d[NNODES];
__device__ float    g_den[NNODES];
__device__ float    g_agg[NNODES * HID];
__device__ float    g_y0[NNODES * HID];
__device__ float    g_y1[NNODES * HID];
__device__ float    g_y4[NNODES * HID];
__device__ float    g_we[4];
// B fragments (fp16 hi only), mma register order:
// layers 0-3 (NT=16): 8192 u32 each; layer 4 (NT=20): 10240 u32
__device__ uint32_t g_Bfrag[4 * 8192 + 10240];

__device__ __forceinline__ void mma_f16(float* c, const uint32_t* a, const uint32_t* b) {
    asm volatile(
        "mma.sync.aligned.m16n8k16.row.col.f32.f16.f16.f32 "
        "{%0,%1,%2,%3}, {%4,%5,%6,%7}, {%8,%9}, {%0,%1,%2,%3};"
        : "+f"(c[0]), "+f"(c[1]), "+f"(c[2]), "+f"(c[3])
        : "r"(a[0]), "r"(a[1]), "r"(a[2]), "r"(a[3]), "r"(b[0]), "r"(b[1]));
}

// ---------------- tiny prep: w = We @ ae for both GAT layers ----------------
__global__ void k_prep_we(const float* __restrict__ We1, const float* __restrict__ ae1,
                          const float* __restrict__ We2, const float* __restrict__ ae2) {
    int t = threadIdx.x;
    if (t < 4) {
        const float* W = (t < 2) ? We1 : We2;
        const float* a = (t < 2) ? ae1 : ae2;
        int r = t & 1;
        float s = 0.f;
        for (int j = 0; j < HID; j++) s += W[r * HID + j] * a[j];
        g_we[t] = s;
    }
}

// ---------------- B fragment prep: W[128,Nreal] fp32 -> fp16 (hi) mma fragments ----
// Fragment layout: idx = ((kt*NT + nt)*32 + lane); 2 u32 per idx: {hi0, hi1}.
__global__ void k_prep_bfrag(const float* __restrict__ W, int Nreal, int NT,
                             uint32_t* __restrict__ out) {
    int idx = blockIdx.x * blockDim.x + threadIdx.x;
    if (idx >= 8 * NT * 32) return;
    int lane = idx & 31;
    int nt = (idx >> 5) % NT;
    int kt = idx / (NT * 32);
    int g = lane >> 2, t = lane & 3;
    int n = nt * 8 + g;
    int k0 = kt * 16 + t * 2;
    float w0 = (n < Nreal) ? __ldg(W + (k0 + 0) * Nreal + n) : 0.f;
    float w1 = (n < Nreal) ? __ldg(W + (k0 + 1) * Nreal + n) : 0.f;
    float w2 = (n < Nreal) ? __ldg(W + (k0 + 8) * Nreal + n) : 0.f;
    float w3 = (n < Nreal) ? __ldg(W + (k0 + 9) * Nreal + n) : 0.f;
    __half2 h0 = __floats2half2_rn(w0, w1);
    __half2 h1 = __floats2half2_rn(w2, w3);
    uint32_t* o = out + (size_t)idx * 2;
    o[0] = *reinterpret_cast<uint32_t*>(&h0);
    o[1] = *reinterpret_cast<uint32_t*>(&h1);
}

// ---------------- per-call re-init of aggregation scratch ----------------
__global__ void k_init() {
    int gid = blockIdx.x * blockDim.x + threadIdx.x;
    if (gid < NNODES * HID) g_agg[gid] = 0.f;
    if (gid < NNODES) g_den[gid] = 0.f;
}

// ---------------- node GEMM (small, stays fp32 scalar) ----------------
template <int K, int MODE>
__global__ __launch_bounds__(128) void k_node_gemm(
    const float* __restrict__ X, const float* __restrict__ X2,
    const float* __restrict__ W, const float* __restrict__ v1,
    const float* __restrict__ v2,
    float* __restrict__ H, float* __restrict__ S, float* __restrict__ D) {
    __shared__ float Ws[K * HID];
    __shared__ float sv1[HID], sv2[HID];
    int tid = threadIdx.x;
    for (int i = tid; i < K * HID; i += 128) Ws[i] = W[i];
    if (tid < HID) {
        sv1[tid] = v1 ? v1[tid] : 0.f;
        sv2[tid] = v2 ? v2[tid] : 0.f;
    }
    __syncthreads();
    int node = blockIdx.x * 128 + tid;
    if (node >= NNODES) return;

    float acc[HID];
#pragma unroll
    for (int n = 0; n < HID; n++) acc[n] = 0.f;

    const float4* xr = reinterpret_cast<const float4*>(X + (size_t)node * K);
    const float4* xr2 = (MODE == 1) ? reinterpret_cast<const float4*>(X2 + (size_t)node * K) : nullptr;
#pragma unroll 1
    for (int k4 = 0; k4 < K / 4; k4++) {
        float4 v = __ldg(xr + k4);
        if (MODE == 1) {
            float4 w = __ldg(xr2 + k4);
            v.x += w.x; v.y += w.y; v.z += w.z; v.w += w.w;
        }
        float xv[4] = {v.x, v.y, v.z, v.w};
#pragma unroll
        for (int kk = 0; kk < 4; kk++) {
            const float* wr = &Ws[(k4 * 4 + kk) * HID];
#pragma unroll
            for (int n = 0; n < HID; n++) acc[n] = fmaf(xv[kk], wr[n], acc[n]);
        }
    }

    if (MODE == 0) {
        float s = 0.f, d = 0.f;
#pragma unroll
        for (int n = 0; n < HID; n++) { s += acc[n] * sv1[n]; d += acc[n] * sv2[n]; }
        S[node] = s;
        D[node] = d;
    } else {
#pragma unroll
        for (int n = 0; n < HID; n++) acc[n] = fmaxf(acc[n] + sv1[n], 0.f);
    }
    float4* hr = reinterpret_cast<float4*>(H + (size_t)node * HID);
#pragma unroll
    for (int i = 0; i < HID / 4; i++)
        hr[i] = make_float4(acc[4 * i], acc[4 * i + 1], acc[4 * i + 2], acc[4 * i + 3]);
}

// ---------------- fused edge pass: logit + exp (no max; logits provably tiny) + agg -----
__global__ __launch_bounds__(256) void k_edge_agg(const int* __restrict__ EI,
                                                  const float* __restrict__ EA, int which) {
    int gid = blockIdx.x * blockDim.x + threadIdx.x;
    int e = gid >> 4;
    int q = gid & 15;
    if (e >= NEDGES) return;
    int lane = threadIdx.x & 31;
    int src = __ldg(EI + e);
    int dst = __ldg(EI + NEDGES + e);
    float ex = 0.f;
    if ((lane & 15) == 0) {
        float w0 = g_we[which * 2], w1 = g_we[which * 2 + 1];
        float lg = g_s[src] + g_d[dst] + __ldg(EA + 2 * e) * w0 + __ldg(EA + 2 * e + 1) * w1;
        lg = (lg > 0.f) ? lg : 0.2f * lg;  // leaky_relu 0.2
        ex = expf(lg);
        atomicAdd(&g_den[dst], ex);
    }
    ex = __shfl_sync(0xffffffffu, ex, lane & 16);
    float4 h4 = *reinterpret_cast<const float4*>(&g_h[(size_t)src * 64 + q * 4]);
    float vx = ex * h4.x, vy = ex * h4.y, vz = ex * h4.z, vw = ex * h4.w;
    asm volatile("red.global.add.v4.f32 [%0], {%1,%2,%3,%4};"
                 :: "l"(&g_agg[(size_t)dst * 64 + q * 4]),
                    "f"(vx), "f"(vy), "f"(vz), "f"(vw)
                 : "memory");
}

// ---------------- normalize + bias + relu ----------------
__global__ void k_node_fin(const float* __restrict__ bias, float* __restrict__ Y) {
    int gid = blockIdx.x * blockDim.x + threadIdx.x;
    if (gid >= NNODES * HID) return;
    int n = gid & 63;
    float den = fmaxf(g_den[gid >> 6], 1e-16f);
    Y[gid] = fmaxf(g_agg[gid] / den + __ldg(bias + n), 0.f);
}

// ================= fully fused edge MLP (gather + 5 fp16-split HMMA layers) =========
// A kept full precision as (hi + lo) fp16; B truncated to fp16 hi (err ~2^-11).
// SMEM map (dynamic, 77696 B):
//   [0, 34816)       A hi  (128 rows x 272 B stride)
//   [34816, 69632)   A lo
//   [0, 74240)       final fp32 staging (reuses A after last mainloop)
//   [74240, 77696)   consts: We0(128f) be0(64f) b0..b3(4x128f) b4(160f)
__device__ __forceinline__ void store_hilo2(char* p, float x, float y) {
    __half2 h = __floats2half2_rn(x, y);
    float2 f = __half22float2(h);
    __half2 l = __floats2half2_rn(x - f.x, y - f.y);
    *reinterpret_cast<uint32_t*>(p) = *reinterpret_cast<uint32_t*>(&h);
    *reinterpret_cast<uint32_t*>(p + 34816) = *reinterpret_cast<uint32_t*>(&l);
}

template <int NTW>
__device__ __forceinline__ void mlp_mainloop(
    const char* sm, const uint32_t* __restrict__ Bf,
    int wm, int wn, int lane, float (&acc)[4][NTW][4]) {
    constexpr int NT = 4 * NTW;
    const int g = lane >> 2, t = lane & 3;
#pragma unroll
    for (int a = 0; a < 4; a++)
#pragma unroll
        for (int b = 0; b < NTW; b++)
#pragma unroll
            for (int c = 0; c < 4; c++) acc[a][b][c] = 0.f;
#pragma unroll 1
    for (int kt = 0; kt < 8; kt++) {
        uint32_t bh[NTW][2];
        const uint32_t* bp = Bf + ((size_t)(kt * NT + wn * NTW) * 32 + lane) * 2;
#pragma unroll
        for (int nt = 0; nt < NTW; nt++) {
            bh[nt][0] = __ldg(bp + nt * 64 + 0);
            bh[nt][1] = __ldg(bp + nt * 64 + 1);
        }
#pragma unroll
        for (int mt = 0; mt < 4; mt++) {
            const char* Ah = sm + (wm * 64 + mt * 16 + g) * 272 + (kt * 16 + t * 2) * 2;
            uint32_t ah[4], al[4];
            ah[0] = *reinterpret_cast<const uint32_t*>(Ah);
            ah[1] = *reinterpret_cast<const uint32_t*>(Ah + 8 * 272);
            ah[2] = *reinterpret_cast<const uint32_t*>(Ah + 16);
            ah[3] = *reinterpret_cast<const uint32_t*>(Ah + 8 * 272 + 16);
            al[0] = *reinterpret_cast<const uint32_t*>(Ah + 34816);
            al[1] = *reinterpret_cast<const uint32_t*>(Ah + 34816 + 8 * 272);
            al[2] = *reinterpret_cast<const uint32_t*>(Ah + 34816 + 16);
            al[3] = *reinterpret_cast<const uint32_t*>(Ah + 34816 + 8 * 272 + 16);
#pragma unroll
            for (int nt = 0; nt < NTW; nt++) {
                mma_f16(acc[mt][nt], ah, bh[nt]);
                mma_f16(acc[mt][nt], al, bh[nt]);
            }
        }
    }
}

__global__ __launch_bounds__(256) void k_mlp(
    const int* __restrict__ EI, const float* __restrict__ EA,
    const float* __restrict__ Y4, const uint32_t* __restrict__ Bf,
    const float* __restrict__ We0, const float* __restrict__ be0,
    const float* __restrict__ b3, const float* __restrict__ bm0,
    const float* __restrict__ bm1, const float* __restrict__ bm2,
    const float* __restrict__ b4, float* __restrict__ out) {
    extern __shared__ char sm[];
    float* cs = reinterpret_cast<float*>(sm + 74240);
    const int tid = threadIdx.x;
    const int wid = tid >> 5, lane = tid & 31;
    const int g = lane >> 2, t = lane & 3;
    const int wm = wid >> 2, wn = wid & 3;
    const int m0 = blockIdx.x * 128;

    // consts -> smem
    for (int i = tid; i < 128; i += 256) {
        cs[i] = __ldg(We0 + i);
        cs[192 + i] = __ldg(b3 + i);
        cs[320 + i] = __ldg(bm0 + i);
        cs[448 + i] = __ldg(bm1 + i);
        cs[576 + i] = __ldg(bm2 + i);
    }
    for (int i = tid; i < 64; i += 256) cs[128 + i] = __ldg(be0 + i);
    for (int i = tid; i < 160; i += 256) cs[704 + i] = (i < 145) ? __ldg(b4 + i) : 0.f;
    __syncthreads();

    // stage layer-0 input: [y4[src]+y4[dst] | relu(ea@We0+be0)] -> hi/lo fp16 SMEM
#pragma unroll
    for (int it = 0; it < 16; it++) {
        int i = tid + it * 256;
        int row = i >> 5, col = (i & 31) * 4;
        int e = m0 + row;
        float4 v;
        if (col < 64) {
            int s = __ldg(EI + e), d = __ldg(EI + NEDGES + e);
            float4 a = *reinterpret_cast<const float4*>(Y4 + (size_t)s * 64 + col);
            float4 b = *reinterpret_cast<const float4*>(Y4 + (size_t)d * 64 + col);
            v = make_float4(a.x + b.x, a.y + b.y, a.z + b.z, a.w + b.w);
        } else {
            int c2 = col - 64;
            float e0 = __ldg(EA + 2 * e), e1 = __ldg(EA + 2 * e + 1);
            v.x = fmaxf(e0 * cs[c2 + 0] + e1 * cs[64 + c2 + 0] + cs[128 + c2 + 0], 0.f);
            v.y = fmaxf(e0 * cs[c2 + 1] + e1 * cs[64 + c2 + 1] + cs[128 + c2 + 1], 0.f);
            v.z = fmaxf(e0 * cs[c2 + 2] + e1 * cs[64 + c2 + 2] + cs[128 + c2 + 2], 0.f);
            v.w = fmaxf(e0 * cs[c2 + 3] + e1 * cs[64 + c2 + 3] + cs[128 + c2 + 3], 0.f);
        }
        char* p = sm + row * 272 + col * 2;
        store_hilo2(p, v.x, v.y);
        store_hilo2(p + 4, v.z, v.w);
    }
    __syncthreads();

    // 4 hidden layers, resident in SMEM
#pragma unroll 1
    for (int l = 0; l < 4; l++) {
        float acc[4][4][4];
        mlp_mainloop<4>(sm, Bf + l * 8192, wm, wn, lane, acc);
        __syncthreads();  // all A reads done before overwrite
        const float* bs = cs + 192 + l * 128;
#pragma unroll
        for (int mt = 0; mt < 4; mt++) {
            int r0 = wm * 64 + mt * 16 + g;
#pragma unroll
            for (int nt = 0; nt < 4; nt++) {
                int c0 = wn * 32 + nt * 8 + t * 2;
                float bv0 = bs[c0], bv1 = bs[c0 + 1];
                char* p0 = sm + r0 * 272 + c0 * 2;
                store_hilo2(p0, fmaxf(acc[mt][nt][0] + bv0, 0.f),
                                fmaxf(acc[mt][nt][1] + bv1, 0.f));
                store_hilo2(p0 + 8 * 272, fmaxf(acc[mt][nt][2] + bv0, 0.f),
                                          fmaxf(acc[mt][nt][3] + bv1, 0.f));
            }
        }
        __syncthreads();
    }

    // final layer: 160 padded cols, 145 real
    {
        float acc[4][5][4];
        mlp_mainloop<5>(sm, Bf + 4 * 8192, wm, wn, lane, acc);
        __syncthreads();
        float* epi = reinterpret_cast<float*>(sm);
        const float* bs = cs + 704;
#pragma unroll
        for (int mt = 0; mt < 4; mt++) {
            int r0 = wm * 64 + mt * 16 + g;
#pragma unroll
            for (int nt = 0; nt < 5; nt++) {
                int c0 = wn * 40 + nt * 8 + t * 2;
                float bv0 = bs[c0], bv1 = bs[c0 + 1];
                if (c0 < 145) {
                    epi[r0 * 145 + c0] = acc[mt][nt][0] + bv0;
                    epi[(r0 + 8) * 145 + c0] = acc[mt][nt][2] + bv0;
                }
                if (c0 + 1 < 145) {
                    epi[r0 * 145 + c0 + 1] = acc[mt][nt][1] + bv1;
                    epi[(r0 + 8) * 145 + c0 + 1] = acc[mt][nt][3] + bv1;
                }
            }
        }
        __syncthreads();
        float* Co = out + (size_t)m0 * 145;
        for (int i = tid; i < 128 * 145; i += 256) Co[i] = epi[i];
    }
}

// ---------------- launch ----------------
extern "C" void kernel_launch(void* const* d_in, const int* in_sizes, int n_in,
                              void* d_out, int out_size) {
    const float* x   = (const float*)d_in[0];
    const int*   ei  = (const int*)d_in[1];
    const float* ea  = (const float*)d_in[2];
    const float* Wg1 = (const float*)d_in[4];
    const float* as1 = (const float*)d_in[5];
    const float* ad1 = (const float*)d_in[6];
    const float* We1 = (const float*)d_in[7];
    const float* ae1 = (const float*)d_in[8];
    const float* bg1 = (const float*)d_in[9];
    const float* Wg2 = (const float*)d_in[10];
    const float* as2 = (const float*)d_in[11];
    const float* ad2 = (const float*)d_in[12];
    const float* We2 = (const float*)d_in[13];
    const float* ae2 = (const float*)d_in[14];
    const float* bg2 = (const float*)d_in[15];
    const float* W2  = (const float*)d_in[16];
    const float* b2  = (const float*)d_in[17];
    const float* We0 = (const float*)d_in[18];
    const float* be0 = (const float*)d_in[19];
    const float* W3  = (const float*)d_in[20];
    const float* b3  = (const float*)d_in[21];
    const float* Wm0 = (const float*)d_in[22];
    const float* bm0 = (const float*)d_in[23];
    const float* Wm1 = (const float*)d_in[24];
    const float* bm1 = (const float*)d_in[25];
    const float* Wm2 = (const float*)d_in[26];
    const float* bm2 = (const float*)d_in[27];
    const float* W4  = (const float*)d_in[28];
    const float* b4  = (const float*)d_in[29];
    float* out = (float*)d_out;

    float *p_h, *p_s, *p_d, *p_y0, *p_y1, *p_y4;
    uint32_t* p_BF;
    cudaGetSymbolAddress((void**)&p_h, g_h);
    cudaGetSymbolAddress((void**)&p_s, g_s);
    cudaGetSymbolAddress((void**)&p_d, g_d);
    cudaGetSymbolAddress((void**)&p_y0, g_y0);
    cudaGetSymbolAddress((void**)&p_y1, g_y1);
    cudaGetSymbolAddress((void**)&p_y4, g_y4);
    cudaGetSymbolAddress((void**)&p_BF, g_Bfrag);

    const int SMM = 77696;  // dynamic smem for k_mlp
    cudaFuncSetAttribute(k_mlp, cudaFuncAttributeMaxDynamicSharedMemorySize, SMM);

    const int initGrid = (NNODES * HID + 255) / 256;
    const int nodeGrid = (NNODES + 127) / 128;
    const int aggGrid  = (NEDGES * 16) / 256;  // 50000

    k_prep_we<<<1, 32>>>(We1, ae1, We2, ae2);

    // B fragments for the 5 tensor GEMMs (fp16 hi only)
    k_prep_bfrag<<<(8 * 16 * 32 + 255) / 256, 256>>>(W3,  128, 16, p_BF + 0 * 8192);
    k_prep_bfrag<<<(8 * 16 * 32 + 255) / 256, 256>>>(Wm0, 128, 16, p_BF + 1 * 8192);
    k_prep_bfrag<<<(8 * 16 * 32 + 255) / 256, 256>>>(Wm1, 128, 16, p_BF + 2 * 8192);
    k_prep_bfrag<<<(8 * 16 * 32 + 255) / 256, 256>>>(Wm2, 128, 16, p_BF + 3 * 8192);
    k_prep_bfrag<<<(8 * 20 * 32 + 255) / 256, 256>>>(W4,  145, 20, p_BF + 4 * 8192);

    // ---- GAT layer 1 ----
    k_init<<<initGrid, 256>>>();
    k_node_gemm<128, 0><<<nodeGrid, 128>>>(x, nullptr, Wg1, as1, ad1, p_h, p_s, p_d);
    k_edge_agg<<<aggGrid, 256>>>(ei, ea, 0);
    k_node_fin<<<initGrid, 256>>>(bg1, p_y0);

    // ---- GAT layer 2 ----
    k_init<<<initGrid, 256>>>();
    k_node_gemm<64, 0><<<nodeGrid, 128>>>(p_y0, nullptr, Wg2, as2, ad2, p_h, p_s, p_d);
    k_edge_agg<<<aggGrid, 256>>>(ei, ea, 1);
    k_node_fin<<<initGrid, 256>>>(bg2, p_y1);

    // ---- l2: y4 = relu((y0+y1) @ W2 + b2) ----
    k_node_gemm<64, 1><<<nodeGrid, 128>>>(p_y0, p_y1, W2, b2, nullptr, p_y4, nullptr, nullptr);

    // ---- fully fused edge MLP (fp16 2-term split) ----
    k_mlp<<<NEDGES / 128, 256, SMM>>>(ei, ea, p_y4, p_BF, We0, be0, b3, bm0, bm1, bm2, b4, out);
}